// round 11
// baseline (speedup 1.0000x reference)
#include <cuda_runtime.h>
#include <cuda_fp16.h>
#include <cstdint>

#define Bn 2
#define Sn 2048
#define Dn 1024
#define Hn 16

#define KSTR 72    // K/V tile: halves per row (64 + 8 pad)
#define PSTR 72
// 1/sqrt(64) * log2(e): exp(s) == ex2(s_scaled)
#define QSCALE 0.18033688011112042f

// fp16 scratch (static device arrays, no allocation):
__device__ __half g_ctxh[(size_t)Bn * Sn * Dn];   // attention output
__device__ __half g_Wh[(size_t)Dn * Dn];          // W in fp16
__device__ __half g_Kh[(size_t)Bn * Hn * Sn * 64];   // K [bh][s][d] fp16
__device__ __half g_Vh[(size_t)Bn * Hn * Sn * 64];   // V [bh][s][d] fp16 (row-major!)

// ---------------- helpers ----------------
__device__ __forceinline__ uint32_t smem_u32(const void* p) {
    uint32_t a;
    asm("{ .reg .u64 t; cvta.to.shared.u64 t, %1; cvt.u32.u64 %0, t; }" : "=r"(a) : "l"(p));
    return a;
}
// pack two fp32 -> half2 (first arg = low half)
__device__ __forceinline__ uint32_t packh2(float lo, float hi) {
    uint32_t d;
    asm("cvt.rn.f16x2.f32 %0, %1, %2;" : "=r"(d) : "f"(hi), "f"(lo));
    return d;
}
// 2^x on both halves of packed f16x2
__device__ __forceinline__ uint32_t ex2h2(uint32_t x) {
    uint32_t d;
    asm("ex2.approx.f16x2 %0, %1;" : "=r"(d) : "r"(x));
    return d;
}
// fp32-accumulator fp16 MMA (PV, projection)
__device__ __forceinline__ void mma16(float* c, const uint32_t* a, uint32_t b0, uint32_t b1) {
    asm volatile(
        "mma.sync.aligned.m16n8k16.row.col.f32.f16.f16.f32 "
        "{%0,%1,%2,%3}, {%4,%5,%6,%7}, {%8,%9}, {%0,%1,%2,%3};"
        : "+f"(c[0]), "+f"(c[1]), "+f"(c[2]), "+f"(c[3])
        : "r"(a[0]), "r"(a[1]), "r"(a[2]), "r"(a[3]), "r"(b0), "r"(b1));
}
// fp16-accumulator fp16 MMA (QK scores)
__device__ __forceinline__ void mma16h(uint32_t* c, const uint32_t* a, uint32_t b0, uint32_t b1) {
    asm volatile(
        "mma.sync.aligned.m16n8k16.row.col.f16.f16.f16.f16 "
        "{%0,%1}, {%2,%3,%4,%5}, {%6,%7}, {%0,%1};"
        : "+r"(c[0]), "+r"(c[1])
        : "r"(a[0]), "r"(a[1]), "r"(a[2]), "r"(a[3]), "r"(b0), "r"(b1));
}
__device__ __forceinline__ void cpasync16(uint32_t dst, const void* src) {
    asm volatile("cp.async.cg.shared.global [%0], [%1], 16;" :: "r"(dst), "l"(src));
}
#define CP_COMMIT() asm volatile("cp.async.commit_group;" ::: "memory")
#define CP_WAIT(n)  asm volatile("cp.async.wait_group %0;" :: "n"(n) : "memory")
#define LDSM_X4(r, addr)                                                              \
    asm volatile("ldmatrix.sync.aligned.m8n8.x4.shared.b16 {%0,%1,%2,%3}, [%4];"      \
                 : "=r"((r)[0]), "=r"((r)[1]), "=r"((r)[2]), "=r"((r)[3]) : "r"(addr))
#define LDSM_X4_T(r, addr)                                                            \
    asm volatile("ldmatrix.sync.aligned.m8n8.x4.trans.shared.b16 {%0,%1,%2,%3}, [%4];"\
                 : "=r"((r)[0]), "=r"((r)[1]), "=r"((r)[2]), "=r"((r)[3]) : "r"(addr))

// ---------------------------------------------------------------------------
// Prepass: pure streaming fp32 -> fp16 converts. W -> g_Wh, K -> g_Kh,
// V -> g_Vh (row-major, same as K; transpose handled by ldmatrix.trans).
// ---------------------------------------------------------------------------
__global__ void __launch_bounds__(256)
prep_kernel(const float* __restrict__ K, const float* __restrict__ V,
            const float* __restrict__ W) {
    const int tid = threadIdx.x;
    const int cta = blockIdx.x;

    // W -> Wh (1024 CTAs x 1024 elems = exact cover)
    {
        size_t base = (size_t)cta * 1024 + tid * 4;
        float4 w4 = *(const float4*)(W + base);
        *(uint2*)(g_Wh + base) = make_uint2(packh2(w4.x, w4.y), packh2(w4.z, w4.w));
    }

    const int bh = cta >> 5, kt = cta & 31;
    const int b = bh >> 4, h = bh & 15;
    const int n0 = kt * 64;
    const float* Kg = K + (size_t)b * Sn * Dn + h * 64;
    const float* Vg = V + (size_t)b * Sn * Dn + h * 64;

    __half* kd = g_Kh + (size_t)bh * Sn * 64 + (size_t)n0 * 64;
    __half* vd = g_Vh + (size_t)bh * Sn * 64 + (size_t)n0 * 64;
#pragma unroll
    for (int j = 0; j < 4; j++) {
        int idx = j * 256 + tid;
        int r = idx >> 4, c4 = (idx & 15) * 4;
        float4 kv = *(const float4*)(Kg + (size_t)(n0 + r) * Dn + c4);
        *(uint2*)(kd + r * 64 + c4) = make_uint2(packh2(kv.x, kv.y), packh2(kv.z, kv.w));
        float4 vv = *(const float4*)(Vg + (size_t)(n0 + r) * Dn + c4);
        *(uint2*)(vd + r * 64 + c4) = make_uint2(packh2(vv.x, vv.y), packh2(vv.z, vv.w));
    }
}

// ---------------------------------------------------------------------------
// Attention: CTA = one (b,h) x 128 q-rows, 128 threads = 4 warps x 32 rows
// (2 m-frags per warp). BN=128 keys/iter, 8 chunks between barriers.
// QK: fp16 accumulators (C-frag layout == PV A-frag layout; ex2.f16x2 in
// place). PV: fp32 accumulators, V B-frags via ldmatrix.x4.TRANS from
// row-major V smem (no transposed global copy needed).
// SMEM: Kst f16[2][128x72] | Vst f16[2][128x72]  (73728 B -> 3 CTAs/SM).
// ---------------------------------------------------------------------------
__global__ void __launch_bounds__(128, 3)
attn_kernel(const float* __restrict__ Q) {
    extern __shared__ char sm[];
    __half* Kst = (__half*)sm;                 // 2 x 18432 B
    __half* Vst = (__half*)(sm + 36864);       // 2 x 18432 B

    const int tid = threadIdx.x;
    const int lane = tid & 31, warp = tid >> 5;
    const int g = lane >> 2, t = lane & 3;
    const int lr = lane & 7;
    const int bh = blockIdx.y;
    const int b = bh >> 4, h = bh & 15;
    const int q0 = blockIdx.x * 128;
    const int arow = warp * 32;

    const __half* Kg = g_Kh + (size_t)bh * Sn * 64;
    const __half* Vg = g_Vh + (size_t)bh * Sn * 64;

    const uint32_t kst_u = smem_u32(Kst);
    const uint32_t vst_u = smem_u32(Vst);

    // prologue: stage 0 of K [128x64] and V [128x64] (identical addressing)
#pragma unroll
    for (int j = 0; j < 8; j++) {
        int idx = j * 128 + tid;
        int r = idx >> 3, c = (idx & 7) * 8;
        cpasync16(kst_u + (uint32_t)(r * KSTR + c) * 2, Kg + (size_t)r * 64 + c);
        cpasync16(vst_u + (uint32_t)(r * KSTR + c) * 2, Vg + (size_t)r * 64 + c);
    }
    CP_COMMIT();

    // Q fragments -> registers (scaled 1/8 * log2e), 2 m-frags
    uint32_t qa[2][4][4];
#pragma unroll
    for (int mf = 0; mf < 2; mf++) {
        const float* q_lo = Q + ((size_t)b * Sn + q0 + arow + mf * 16 + g) * Dn + h * 64 + 2 * t;
        const float* q_hi = q_lo + 8 * Dn;
#pragma unroll
        for (int ksp = 0; ksp < 4; ksp++) {
            float2 x0 = *(const float2*)(q_lo + ksp * 16);
            float2 x1 = *(const float2*)(q_hi + ksp * 16);
            float2 x2 = *(const float2*)(q_lo + ksp * 16 + 8);
            float2 x3 = *(const float2*)(q_hi + ksp * 16 + 8);
            qa[mf][ksp][0] = packh2(x0.x * QSCALE, x0.y * QSCALE);
            qa[mf][ksp][1] = packh2(x1.x * QSCALE, x1.y * QSCALE);
            qa[mf][ksp][2] = packh2(x2.x * QSCALE, x2.y * QSCALE);
            qa[mf][ksp][3] = packh2(x3.x * QSCALE, x3.y * QSCALE);
        }
    }

    float o[2][8][4];
    float lsum[2][2];
#pragma unroll
    for (int mf = 0; mf < 2; mf++) {
        lsum[mf][0] = lsum[mf][1] = 0.0f;
#pragma unroll
        for (int n = 0; n < 8; n++)
#pragma unroll
            for (int j = 0; j < 4; j++) o[mf][n][j] = 0.0f;
    }

    const int am_rows = (lane >> 3) & 1;
    const int am_cols = lane >> 4;

    for (int it = 0; it < Sn / 128; ++it) {
        const int st = it & 1;
        CP_WAIT(0);
        __syncthreads();

        if (it + 1 < Sn / 128) {
            const __half* kb = Kg + (size_t)(it + 1) * 128 * 64;
            const __half* vb = Vg + (size_t)(it + 1) * 128 * 64;
            uint32_t kd = kst_u + (uint32_t)(st ^ 1) * (128 * KSTR * 2);
            uint32_t vd = vst_u + (uint32_t)(st ^ 1) * (128 * KSTR * 2);
#pragma unroll
            for (int j = 0; j < 8; j++) {
                int idx = j * 128 + tid;
                int r = idx >> 3, c = (idx & 7) * 8;
                cpasync16(kd + (uint32_t)(r * KSTR + c) * 2, kb + (size_t)r * 64 + c);
                cpasync16(vd + (uint32_t)(r * KSTR + c) * 2, vb + (size_t)r * 64 + c);
            }
        }
        CP_COMMIT();

        const uint32_t ks_u = kst_u + (uint32_t)st * (128 * KSTR * 2);
        const uint32_t vs_u = vst_u + (uint32_t)st * (128 * KSTR * 2);

        // 8 x 16-key chunks: QK(f16 acc) -> ex2.f16x2 -> PV(f32 acc)
#pragma unroll
        for (int c = 0; c < 8; c++) {
            uint32_t scA[2][2] = {{0u, 0u}, {0u, 0u}};
            uint32_t scB[2][2] = {{0u, 0u}, {0u, 0u}};
#pragma unroll
            for (int ksp = 0; ksp < 4; ksp++) {
                uint32_t bb[4];
                LDSM_X4(bb, ks_u + (uint32_t)((c * 16 + am_cols * 8 + lr) * KSTR
                                              + ksp * 16 + am_rows * 8) * 2);
                mma16h(scA[0], qa[0][ksp], bb[0], bb[1]);
                mma16h(scB[0], qa[0][ksp], bb[2], bb[3]);
                mma16h(scA[1], qa[1][ksp], bb[0], bb[1]);
                mma16h(scB[1], qa[1][ksp], bb[2], bb[3]);
            }

            // P = 2^s in place (f16 C-frags ARE the PV A-frags)
            uint32_t pa[2][4];
#pragma unroll
            for (int mf = 0; mf < 2; mf++) {
                pa[mf][0] = ex2h2(scA[mf][0]);
                pa[mf][1] = ex2h2(scA[mf][1]);
                pa[mf][2] = ex2h2(scB[mf][0]);
                pa[mf][3] = ex2h2(scB[mf][1]);
                __half2 s0 = __hadd2(*(__half2*)&pa[mf][0], *(__half2*)&pa[mf][2]);
                __half2 s1 = __hadd2(*(__half2*)&pa[mf][1], *(__half2*)&pa[mf][3]);
                lsum[mf][0] += __low2float(s0) + __high2float(s0);
                lsum[mf][1] += __low2float(s1) + __high2float(s1);
            }

            // PV: B-frags from ROW-MAJOR V via ldmatrix.trans.
            // rows = keys (chunk c), cols = d (nfp*16 block).
#pragma unroll
            for (int nfp = 0; nfp < 4; nfp++) {
                uint32_t bb[4];
                LDSM_X4_T(bb, vs_u + (uint32_t)((c * 16 + am_rows * 8 + lr) * KSTR
                                                + nfp * 16 + am_cols * 8) * 2);
                mma16(o[0][2 * nfp], pa[0], bb[0], bb[1]);
                mma16(o[0][2 * nfp + 1], pa[0], bb[2], bb[3]);
                mma16(o[1][2 * nfp], pa[1], bb[0], bb[1]);
                mma16(o[1][2 * nfp + 1], pa[1], bb[2], bb[3]);
            }
        }
    }

    // Epilogue: quad-reduce l, normalize, write ctx fp16
#pragma unroll
    for (int mf = 0; mf < 2; mf++) {
        float l0 = lsum[mf][0], l1 = lsum[mf][1];
        l0 += __shfl_xor_sync(0xffffffffu, l0, 1);
        l0 += __shfl_xor_sync(0xffffffffu, l0, 2);
        l1 += __shfl_xor_sync(0xffffffffu, l1, 1);
        l1 += __shfl_xor_sync(0xffffffffu, l1, 2);
        const float inv0 = 1.0f / l0, inv1 = 1.0f / l1;
        const int r = q0 + arow + mf * 16 + g;
        __half* d0 = g_ctxh + ((size_t)b * Sn + r) * Dn + h * 64 + 2 * t;
        __half* d1 = g_ctxh + ((size_t)b * Sn + r + 8) * Dn + h * 64 + 2 * t;
#pragma unroll
        for (int nf = 0; nf < 8; nf++) {
            *(uint32_t*)(d0 + nf * 8) = packh2(o[mf][nf][0] * inv0, o[mf][nf][1] * inv0);
            *(uint32_t*)(d1 + nf * 8) = packh2(o[mf][nf][2] * inv1, o[mf][nf][3] * inv1);
        }
    }
}

// ---------------------------------------------------------------------------
// Projection: out[4096,1024] = ctx_f16 @ Wh^T + bias.
// 128x64 tiles -> 512 CTAs, 256 thr = 8 warps (4x2), warp tile 32x32
// (acc = 32 regs -> fits occ 3 => 6 warps/SMSP). 2-stage cp.async.
// SMEM/stage: A 128x72 + B 64x72 = 27648 B; 2 stages = 55296 B.
// ---------------------------------------------------------------------------
__global__ void __launch_bounds__(256, 3)
proj_kernel(const float* __restrict__ bias, float* __restrict__ out) {
    extern __shared__ char psm[];
    const int tid = threadIdx.x, lane = tid & 31, warp = tid >> 5;
    const int g = lane >> 2, t = lane & 3;
    const int lr = lane & 7;
    const int wm = warp >> 1, wn = warp & 1;
    const int j0 = blockIdx.x * 64, i0 = blockIdx.y * 128;
    const int am_rows = (lane >> 3) & 1;
    const int am_cols = lane >> 4;

    const __half* Ab = g_ctxh + (size_t)i0 * Dn;
    const __half* Bb = g_Wh + (size_t)j0 * Dn;
    const uint32_t sbase = smem_u32(psm);

#define PROJ_ISSUE(c, s)                                                           \
    do {                                                                           \
        uint32_t ab = sbase + (uint32_t)(s) * 27648u;                              \
        uint32_t bbp = ab + 18432u;                                                \
        _Pragma("unroll")                                                          \
        for (int j = 0; j < 4; j++) {                                              \
            int idx = j * 256 + tid;                                               \
            int r = idx >> 3, ch = (idx & 7) * 8;                                  \
            cpasync16(ab + (uint32_t)(r * PSTR + ch) * 2,                          \
                      Ab + (size_t)r * Dn + (c) * 64 + ch);                        \
        }                                                                          \
        _Pragma("unroll")                                                          \
        for (int j = 0; j < 2; j++) {                                              \
            int idx = j * 256 + tid;                                               \
            int r = idx >> 3, ch = (idx & 7) * 8;                                  \
            cpasync16(bbp + (uint32_t)(r * PSTR + ch) * 2,                         \
                      Bb + (size_t)r * Dn + (c) * 64 + ch);                        \
        }                                                                          \
    } while (0)

    float acc[2][4][4];
#pragma unroll
    for (int mf = 0; mf < 2; mf++)
#pragma unroll
        for (int nf = 0; nf < 4; nf++)
#pragma unroll
            for (int j = 0; j < 4; j++) acc[mf][nf][j] = 0.0f;

    PROJ_ISSUE(0, 0);
    CP_COMMIT();

    for (int c = 0; c < 16; c++) {
        CP_WAIT(0);
        __syncthreads();
        if (c + 1 < 16) PROJ_ISSUE(c + 1, (c + 1) & 1);
        CP_COMMIT();

        const __half* As = (const __half*)(psm + (c & 1) * 27648);
        const __half* Bs = As + 9216;
#pragma unroll
        for (int ksp = 0; ksp < 4; ksp++) {
            uint32_t a[2][4];
#pragma unroll
            for (int mf = 0; mf < 2; mf++)
                LDSM_X4(a[mf], smem_u32(As + (wm * 32 + mf * 16 + am_rows * 8 + lr) * PSTR
                                           + ksp * 16 + am_cols * 8));
#pragma unroll
            for (int nfp = 0; nfp < 2; nfp++) {
                uint32_t bb[4];
                LDSM_X4(bb, smem_u32(Bs + (wn * 32 + nfp * 16 + am_cols * 8 + lr) * PSTR
                                        + ksp * 16 + am_rows * 8));
#pragma unroll
                for (int mf = 0; mf < 2; mf++) {
                    mma16(acc[mf][2 * nfp], a[mf], bb[0], bb[1]);
                    mma16(acc[mf][2 * nfp + 1], a[mf], bb[2], bb[3]);
                }
            }
        }
    }

#pragma unroll
    for (int mf = 0; mf < 2; mf++) {
        const int r0 = i0 + wm * 32 + mf * 16 + g;
#pragma unroll
        for (int nf = 0; nf < 4; nf++) {
            const int col = j0 + wn * 32 + nf * 8 + 2 * t;
            float b0 = __ldg(bias + col), b1 = __ldg(bias + col + 1);
            *(float2*)(out + (size_t)r0 * Dn + col) =
                make_float2(acc[mf][nf][0] + b0, acc[mf][nf][1] + b1);
            *(float2*)(out + (size_t)(r0 + 8) * Dn + col) =
                make_float2(acc[mf][nf][2] + b0, acc[mf][nf][3] + b1);
        }
    }
#undef PROJ_ISSUE
}

extern "C" void kernel_launch(void* const* d_in, const int* in_sizes, int n_in,
                              void* d_out, int out_size) {
    const float* q    = (const float*)d_in[0];
    const float* k    = (const float*)d_in[1];
    const float* v    = (const float*)d_in[2];
    const float* w    = (const float*)d_in[3];
    const float* bias = (const float*)d_in[4];
    float* out = (float*)d_out;

    const int ASMEM = 73728;   // 2-stage K + 2-stage V (both 128x72 fp16)
    const int PSMEM = 55296;   // 2 stages x (A 128x72 + B 64x72)
    cudaFuncSetAttribute(attn_kernel, cudaFuncAttributeMaxDynamicSharedMemorySize, ASMEM);
    cudaFuncSetAttribute(proj_kernel, cudaFuncAttributeMaxDynamicSharedMemorySize, PSMEM);

    prep_kernel<<<1024, 256>>>(k, v, w);
    attn_kernel<<<dim3(Sn / 128, Bn * Hn), 128, ASMEM>>>(q);
    proj_kernel<<<dim3(Dn / 64, (Bn * Sn) / 128), 256, PSMEM>>>(bias, out);
}

// round 12
// speedup vs baseline: 1.0739x; 1.0739x over previous
#include <cuda_runtime.h>
#include <cuda_fp16.h>
#include <cstdint>

#define Bn 2
#define Sn 2048
#define Dn 1024
#define Hn 16

#define KSTR 72    // K tile: halves per row (64 + 8 pad)
#define VSTR 136   // Vt tile: halves per row (128 + 8 pad)
#define PSTR 72
// 1/sqrt(64) * log2(e): exp(s) == ex2(s_scaled)
#define QSCALE 0.18033688011112042f

// fp16 scratch (static device arrays, no allocation):
__device__ __half g_ctxh[(size_t)Bn * Sn * Dn];   // attention output
__device__ __half g_Wh[(size_t)Dn * Dn];          // W in fp16
__device__ __half g_Kh[(size_t)Bn * Hn * Sn * 64];   // K  [bh][s][d] fp16
__device__ __half g_Vth[(size_t)Bn * Hn * 64 * Sn];  // V^T [bh][d][s] fp16

// ---------------- helpers ----------------
__device__ __forceinline__ uint32_t smem_u32(const void* p) {
    uint32_t a;
    asm("{ .reg .u64 t; cvta.to.shared.u64 t, %1; cvt.u32.u64 %0, t; }" : "=r"(a) : "l"(p));
    return a;
}
// pack two fp32 -> half2 (first arg = low half)
__device__ __forceinline__ uint32_t packh2(float lo, float hi) {
    uint32_t d;
    asm("cvt.rn.f16x2.f32 %0, %1, %2;" : "=r"(d) : "f"(hi), "f"(lo));
    return d;
}
// 2^x on both halves of packed f16x2
__device__ __forceinline__ uint32_t ex2h2(uint32_t x) {
    uint32_t d;
    asm("ex2.approx.f16x2 %0, %1;" : "=r"(d) : "r"(x));
    return d;
}
// fp32-accumulator fp16 MMA (PV, projection)
__device__ __forceinline__ void mma16(float* c, const uint32_t* a, uint32_t b0, uint32_t b1) {
    asm volatile(
        "mma.sync.aligned.m16n8k16.row.col.f32.f16.f16.f32 "
        "{%0,%1,%2,%3}, {%4,%5,%6,%7}, {%8,%9}, {%0,%1,%2,%3};"
        : "+f"(c[0]), "+f"(c[1]), "+f"(c[2]), "+f"(c[3])
        : "r"(a[0]), "r"(a[1]), "r"(a[2]), "r"(a[3]), "r"(b0), "r"(b1));
}
// fp16-accumulator fp16 MMA (QK scores)
__device__ __forceinline__ void mma16h(uint32_t* c, const uint32_t* a, uint32_t b0, uint32_t b1) {
    asm volatile(
        "mma.sync.aligned.m16n8k16.row.col.f16.f16.f16.f16 "
        "{%0,%1}, {%2,%3,%4,%5}, {%6,%7}, {%0,%1};"
        : "+r"(c[0]), "+r"(c[1])
        : "r"(a[0]), "r"(a[1]), "r"(a[2]), "r"(a[3]), "r"(b0), "r"(b1));
}
__device__ __forceinline__ void cpasync16(uint32_t dst, const void* src) {
    asm volatile("cp.async.cg.shared.global [%0], [%1], 16;" :: "r"(dst), "l"(src));
}
#define CP_COMMIT() asm volatile("cp.async.commit_group;" ::: "memory")
#define CP_WAIT(n)  asm volatile("cp.async.wait_group %0;" :: "n"(n) : "memory")
#define LDSM_X4(r, addr)                                                              \
    asm volatile("ldmatrix.sync.aligned.m8n8.x4.shared.b16 {%0,%1,%2,%3}, [%4];"      \
                 : "=r"((r)[0]), "=r"((r)[1]), "=r"((r)[2]), "=r"((r)[3]) : "r"(addr))

// ---------------------------------------------------------------------------
// Prepass (round-10 version): W -> fp16, K -> fp16 [bh][s][d],
// V -> fp16 transposed [bh][d][s].
// ---------------------------------------------------------------------------
__global__ void __launch_bounds__(256)
prep_kernel(const float* __restrict__ K, const float* __restrict__ V,
            const float* __restrict__ W) {
    __shared__ float sv[64 * 65];
    const int tid = threadIdx.x;
    const int cta = blockIdx.x;

    // W -> Wh (1024 CTAs x 1024 elems = exact cover)
    {
        size_t base = (size_t)cta * 1024 + tid * 4;
        float4 w4 = *(const float4*)(W + base);
        *(uint2*)(g_Wh + base) = make_uint2(packh2(w4.x, w4.y), packh2(w4.z, w4.w));
    }

    const int bh = cta >> 5, kt = cta & 31;
    const int b = bh >> 4, h = bh & 15;
    const int n0 = kt * 64;
    const float* Kg = K + (size_t)b * Sn * Dn + h * 64;
    const float* Vg = V + (size_t)b * Sn * Dn + h * 64;

    __half* kd = g_Kh + (size_t)bh * Sn * 64 + (size_t)n0 * 64;
#pragma unroll
    for (int j = 0; j < 4; j++) {
        int idx = j * 256 + tid;
        int r = idx >> 4, c4 = (idx & 15) * 4;
        float4 kv = *(const float4*)(Kg + (size_t)(n0 + r) * Dn + c4);
        *(uint2*)(kd + r * 64 + c4) = make_uint2(packh2(kv.x, kv.y), packh2(kv.z, kv.w));
    }

#pragma unroll
    for (int j = 0; j < 4; j++) {
        int idx = j * 256 + tid;
        int r = idx >> 4, c4 = (idx & 15) * 4;
        float4 vv = *(const float4*)(Vg + (size_t)(n0 + r) * Dn + c4);
        sv[r * 65 + c4 + 0] = vv.x;
        sv[r * 65 + c4 + 1] = vv.y;
        sv[r * 65 + c4 + 2] = vv.z;
        sv[r * 65 + c4 + 3] = vv.w;
    }
    __syncthreads();
    {
        const int d = tid >> 2;
        const int kc = (tid & 3) * 16;
        __half* vd = g_Vth + (size_t)bh * 64 * Sn + (size_t)d * Sn + n0 + kc;
        uint32_t o[8];
#pragma unroll
        for (int k = 0; k < 8; k++)
            o[k] = packh2(sv[(kc + 2 * k) * 65 + d], sv[(kc + 2 * k + 1) * 65 + d]);
        *(uint4*)(vd) = make_uint4(o[0], o[1], o[2], o[3]);
        *(uint4*)(vd + 8) = make_uint4(o[4], o[5], o[6], o[7]);
    }
}

// ---------------------------------------------------------------------------
// Attention: CTA = one (b,h) x 64 q-rows (grid 1024 -> near-perfect SM
// load balance: max 7x8192 = 57.3k MMAs/SM vs ideal 56.7k).
// 128 threads = 4 warps x 16 rows (1 m-frag). BN=128 keys/iter,
// 8 chunks between barriers. QK fp16 accumulators + in-place ex2.f16x2;
// PV fp32 accumulators. SMEM: Kst[2][128x72] | Vst[2][64x136] (71680 B, occ 3).
// ---------------------------------------------------------------------------
__global__ void __launch_bounds__(128, 3)
attn_kernel(const float* __restrict__ Q) {
    extern __shared__ char sm[];
    __half* Kst = (__half*)sm;                 // 2 x 18432 B
    __half* Vst = (__half*)(sm + 36864);       // 2 x 17408 B

    const int tid = threadIdx.x;
    const int lane = tid & 31, warp = tid >> 5;
    const int g = lane >> 2, t = lane & 3;
    const int lr = lane & 7;
    const int bh = blockIdx.y;
    const int b = bh >> 4, h = bh & 15;
    const int q0 = blockIdx.x * 64;
    const int arow = warp * 16;

    const __half* Kg = g_Kh + (size_t)bh * Sn * 64;
    const __half* VTg = g_Vth + (size_t)bh * 64 * Sn;

    const uint32_t kst_u = smem_u32(Kst);
    const uint32_t vst_u = smem_u32(Vst);

    // prologue: stage 0 of K [128x64] and Vt [64x128]
#pragma unroll
    for (int j = 0; j < 8; j++) {
        int idx = j * 128 + tid;
        int kr = idx >> 3, kc = (idx & 7) * 8;
        cpasync16(kst_u + (uint32_t)(kr * KSTR + kc) * 2, Kg + (size_t)kr * 64 + kc);
        int vr = idx >> 4, vc = (idx & 15) * 8;
        cpasync16(vst_u + (uint32_t)(vr * VSTR + vc) * 2, VTg + (size_t)vr * Sn + vc);
    }
    CP_COMMIT();

    // Q fragments -> registers (scaled 1/8 * log2e), 1 m-frag (16 rows)
    uint32_t qa[4][4];
    {
        const float* q_lo = Q + ((size_t)b * Sn + q0 + arow + g) * Dn + h * 64 + 2 * t;
        const float* q_hi = q_lo + 8 * Dn;
#pragma unroll
        for (int ksp = 0; ksp < 4; ksp++) {
            float2 x0 = *(const float2*)(q_lo + ksp * 16);
            float2 x1 = *(const float2*)(q_hi + ksp * 16);
            float2 x2 = *(const float2*)(q_lo + ksp * 16 + 8);
            float2 x3 = *(const float2*)(q_hi + ksp * 16 + 8);
            qa[ksp][0] = packh2(x0.x * QSCALE, x0.y * QSCALE);
            qa[ksp][1] = packh2(x1.x * QSCALE, x1.y * QSCALE);
            qa[ksp][2] = packh2(x2.x * QSCALE, x2.y * QSCALE);
            qa[ksp][3] = packh2(x3.x * QSCALE, x3.y * QSCALE);
        }
    }

    float o[8][4];
    float lsum0 = 0.0f, lsum1 = 0.0f;
#pragma unroll
    for (int n = 0; n < 8; n++)
#pragma unroll
        for (int j = 0; j < 4; j++) o[n][j] = 0.0f;

    const int am_rows = (lane >> 3) & 1;
    const int am_cols = lane >> 4;

    for (int it = 0; it < Sn / 128; ++it) {
        const int st = it & 1;
        CP_WAIT(0);
        __syncthreads();

        if (it + 1 < Sn / 128) {
            const __half* kb = Kg + (size_t)(it + 1) * 128 * 64;
            const __half* vb = VTg + (it + 1) * 128;
            uint32_t kd = kst_u + (uint32_t)(st ^ 1) * (128 * KSTR * 2);
            uint32_t vd = vst_u + (uint32_t)(st ^ 1) * (64 * VSTR * 2);
#pragma unroll
            for (int j = 0; j < 8; j++) {
                int idx = j * 128 + tid;
                int kr = idx >> 3, kc = (idx & 7) * 8;
                cpasync16(kd + (uint32_t)(kr * KSTR + kc) * 2, kb + (size_t)kr * 64 + kc);
                int vr = idx >> 4, vc = (idx & 15) * 8;
                cpasync16(vd + (uint32_t)(vr * VSTR + vc) * 2, vb + (size_t)vr * Sn + vc);
            }
        }
        CP_COMMIT();

        const uint32_t ks_u = kst_u + (uint32_t)st * (128 * KSTR * 2);
        const uint32_t vs_u = vst_u + (uint32_t)st * (64 * VSTR * 2);

        // 8 x 16-key chunks: QK(f16 acc) -> ex2.f16x2 -> PV(f32 acc)
#pragma unroll
        for (int c = 0; c < 8; c++) {
            uint32_t scA[2] = {0u, 0u};
            uint32_t scB[2] = {0u, 0u};
#pragma unroll
            for (int ksp = 0; ksp < 4; ksp++) {
                uint32_t bb[4];
                LDSM_X4(bb, ks_u + (uint32_t)((c * 16 + am_cols * 8 + lr) * KSTR
                                              + ksp * 16 + am_rows * 8) * 2);
                mma16h(scA, qa[ksp], bb[0], bb[1]);
                mma16h(scB, qa[ksp], bb[2], bb[3]);
            }

            // P = 2^s in place (f16 C-frags ARE the PV A-frags)
            uint32_t pa[4];
            pa[0] = ex2h2(scA[0]);
            pa[1] = ex2h2(scA[1]);
            pa[2] = ex2h2(scB[0]);
            pa[3] = ex2h2(scB[1]);
            __half2 s0 = __hadd2(*(__half2*)&pa[0], *(__half2*)&pa[2]);
            __half2 s1 = __hadd2(*(__half2*)&pa[1], *(__half2*)&pa[3]);
            lsum0 += __low2float(s0) + __high2float(s0);
            lsum1 += __low2float(s1) + __high2float(s1);

            // PV: k-block = chunk c (cols c*16.. in Vt)
#pragma unroll
            for (int nfp = 0; nfp < 4; nfp++) {
                uint32_t bb[4];
                LDSM_X4(bb, vs_u + (uint32_t)((nfp * 16 + am_cols * 8 + lr) * VSTR
                                              + c * 16 + am_rows * 8) * 2);
                mma16(o[2 * nfp], pa, bb[0], bb[1]);
                mma16(o[2 * nfp + 1], pa, bb[2], bb[3]);
            }
        }
    }

    // Epilogue: quad-reduce l, normalize, write ctx fp16
    lsum0 += __shfl_xor_sync(0xffffffffu, lsum0, 1);
    lsum0 += __shfl_xor_sync(0xffffffffu, lsum0, 2);
    lsum1 += __shfl_xor_sync(0xffffffffu, lsum1, 1);
    lsum1 += __shfl_xor_sync(0xffffffffu, lsum1, 2);
    const float inv0 = 1.0f / lsum0, inv1 = 1.0f / lsum1;
    const int r = q0 + arow + g;
    __half* d0 = g_ctxh + ((size_t)b * Sn + r) * Dn + h * 64 + 2 * t;
    __half* d1 = g_ctxh + ((size_t)b * Sn + r + 8) * Dn + h * 64 + 2 * t;
#pragma unroll
    for (int nf = 0; nf < 8; nf++) {
        *(uint32_t*)(d0 + nf * 8) = packh2(o[nf][0] * inv0, o[nf][1] * inv0);
        *(uint32_t*)(d1 + nf * 8) = packh2(o[nf][2] * inv1, o[nf][3] * inv1);
    }
}

// ---------------------------------------------------------------------------
// Projection (round-10 version): out = ctx_f16 @ Wh^T + bias. 128x128 tiles,
// 256 thr, 8 warps (2x4), warp 64x32. 3-stage cp.async, ldmatrix fragments.
// ---------------------------------------------------------------------------
__global__ void __launch_bounds__(256, 2)
proj_kernel(const float* __restrict__ bias, float* __restrict__ out) {
    extern __shared__ char psm[];
    const int tid = threadIdx.x, lane = tid & 31, warp = tid >> 5;
    const int g = lane >> 2, t = lane & 3;
    const int lr = lane & 7;
    const int wm = warp >> 2, wn = warp & 3;
    const int j0 = blockIdx.x * 128, i0 = blockIdx.y * 128;
    const int am_rows = (lane >> 3) & 1;
    const int am_cols = lane >> 4;

    const __half* Ab = g_ctxh + (size_t)i0 * Dn;
    const __half* Bb = g_Wh + (size_t)j0 * Dn;
    const uint32_t sbase = smem_u32(psm);

#define PROJ_ISSUE(c, s)                                                           \
    do {                                                                           \
        uint32_t ab = sbase + (uint32_t)(s) * 36864u;                              \
        uint32_t bbp = ab + 18432u;                                                \
        _Pragma("unroll")                                                          \
        for (int j = 0; j < 4; j++) {                                              \
            int idx = j * 256 + tid;                                               \
            int r = idx >> 3, ch = (idx & 7) * 8;                                  \
            cpasync16(ab + (uint32_t)(r * PSTR + ch) * 2,                          \
                      Ab + (size_t)r * Dn + (c) * 64 + ch);                        \
            cpasync16(bbp + (uint32_t)(r * PSTR + ch) * 2,                         \
                      Bb + (size_t)r * Dn + (c) * 64 + ch);                        \
        }                                                                          \
    } while (0)

    float acc[4][4][4];
#pragma unroll
    for (int mf = 0; mf < 4; mf++)
#pragma unroll
        for (int nf = 0; nf < 4; nf++)
#pragma unroll
            for (int j = 0; j < 4; j++) acc[mf][nf][j] = 0.0f;

    PROJ_ISSUE(0, 0);
    CP_COMMIT();
    PROJ_ISSUE(1, 1);
    CP_COMMIT();

    for (int c = 0; c < 16; c++) {
        CP_WAIT(1);
        __syncthreads();
        if (c + 2 < 16) PROJ_ISSUE(c + 2, (c + 2) % 3);
        CP_COMMIT();

        const __half* As = (const __half*)(psm + (c % 3) * 36864);
        const __half* Bs = As + 9216;
#pragma unroll
        for (int ksp = 0; ksp < 4; ksp++) {
            uint32_t a[4][4];
#pragma unroll
            for (int mf = 0; mf < 4; mf++)
                LDSM_X4(a[mf], smem_u32(As + (wm * 64 + mf * 16 + am_rows * 8 + lr) * PSTR
                                           + ksp * 16 + am_cols * 8));
#pragma unroll
            for (int nfp = 0; nfp < 2; nfp++) {
                uint32_t bb[4];
                LDSM_X4(bb, smem_u32(Bs + (wn * 32 + nfp * 16 + am_cols * 8 + lr) * PSTR
                                        + ksp * 16 + am_rows * 8));
#pragma unroll
                for (int mf = 0; mf < 4; mf++) {
                    mma16(acc[mf][2 * nfp], a[mf], bb[0], bb[1]);
                    mma16(acc[mf][2 * nfp + 1], a[mf], bb[2], bb[3]);
                }
            }
        }
    }

#pragma unroll
    for (int mf = 0; mf < 4; mf++) {
        const int r0 = i0 + wm * 64 + mf * 16 + g;
#pragma unroll
        for (int nf = 0; nf < 4; nf++) {
            const int col = j0 + wn * 32 + nf * 8 + 2 * t;
            float b0 = __ldg(bias + col), b1 = __ldg(bias + col + 1);
            *(float2*)(out + (size_t)r0 * Dn + col) =
                make_float2(acc[mf][nf][0] + b0, acc[mf][nf][1] + b1);
            *(float2*)(out + (size_t)(r0 + 8) * Dn + col) =
                make_float2(acc[mf][nf][2] + b0, acc[mf][nf][3] + b1);
        }
    }
#undef PROJ_ISSUE
}

extern "C" void kernel_launch(void* const* d_in, const int* in_sizes, int n_in,
                              void* d_out, int out_size) {
    const float* q    = (const float*)d_in[0];
    const float* k    = (const float*)d_in[1];
    const float* v    = (const float*)d_in[2];
    const float* w    = (const float*)d_in[3];
    const float* bias = (const float*)d_in[4];
    float* out = (float*)d_out;

    const int ASMEM = 73728;   // 2-stage K(128x72) + 2-stage Vt(64x136) fp16
    const int PSMEM = 110592;  // 3 stages x (A+B)
    cudaFuncSetAttribute(attn_kernel, cudaFuncAttributeMaxDynamicSharedMemorySize, ASMEM);
    cudaFuncSetAttribute(proj_kernel, cudaFuncAttributeMaxDynamicSharedMemorySize, PSMEM);

    prep_kernel<<<1024, 256>>>(k, v, w);
    attn_kernel<<<dim3(Sn / 64, Bn * Hn), 128, ASMEM>>>(q);
    proj_kernel<<<dim3(Dn / 128, (Bn * Sn) / 128), 256, PSMEM>>>(bias, out);
}

// round 13
// speedup vs baseline: 1.0761x; 1.0020x over previous
#include <cuda_runtime.h>
#include <cuda_fp16.h>
#include <cstdint>

#define Bn 2
#define Sn 2048
#define Dn 1024
#define Hn 16

#define KSTR 72    // K tile: halves per row (64 + 8 pad)
#define VSTR 136   // Vt tile: halves per row (128 + 8 pad)
#define PSTR 72
// 1/sqrt(64) * log2(e): exp(s) == ex2(s_scaled)
#define QSCALE 0.18033688011112042f

// fp16 scratch (static device arrays, no allocation):
__device__ __half g_ctxh[(size_t)Bn * Sn * Dn];   // attention output
__device__ __half g_Wh[(size_t)Dn * Dn];          // W in fp16
__device__ __half g_Kh[(size_t)Bn * Hn * Sn * 64];   // K  [bh][s][d] fp16
__device__ __half g_Vth[(size_t)Bn * Hn * 64 * Sn];  // V^T [bh][d][s] fp16

// ---------------- helpers ----------------
__device__ __forceinline__ uint32_t smem_u32(const void* p) {
    uint32_t a;
    asm("{ .reg .u64 t; cvta.to.shared.u64 t, %1; cvt.u32.u64 %0, t; }" : "=r"(a) : "l"(p));
    return a;
}
// pack two fp32 -> half2 (first arg = low half)
__device__ __forceinline__ uint32_t packh2(float lo, float hi) {
    uint32_t d;
    asm("cvt.rn.f16x2.f32 %0, %1, %2;" : "=r"(d) : "f"(hi), "f"(lo));
    return d;
}
// 2^x on both halves of packed f16x2
__device__ __forceinline__ uint32_t ex2h2(uint32_t x) {
    uint32_t d;
    asm("ex2.approx.f16x2 %0, %1;" : "=r"(d) : "r"(x));
    return d;
}
// fp32-accumulator fp16 MMA (PV, projection)
__device__ __forceinline__ void mma16(float* c, const uint32_t* a, uint32_t b0, uint32_t b1) {
    asm volatile(
        "mma.sync.aligned.m16n8k16.row.col.f32.f16.f16.f32 "
        "{%0,%1,%2,%3}, {%4,%5,%6,%7}, {%8,%9}, {%0,%1,%2,%3};"
        : "+f"(c[0]), "+f"(c[1]), "+f"(c[2]), "+f"(c[3])
        : "r"(a[0]), "r"(a[1]), "r"(a[2]), "r"(a[3]), "r"(b0), "r"(b1));
}
// fp16-accumulator fp16 MMA (QK scores)
__device__ __forceinline__ void mma16h(uint32_t* c, const uint32_t* a, uint32_t b0, uint32_t b1) {
    asm volatile(
        "mma.sync.aligned.m16n8k16.row.col.f16.f16.f16.f16 "
        "{%0,%1}, {%2,%3,%4,%5}, {%6,%7}, {%0,%1};"
        : "+r"(c[0]), "+r"(c[1])
        : "r"(a[0]), "r"(a[1]), "r"(a[2]), "r"(a[3]), "r"(b0), "r"(b1));
}
__device__ __forceinline__ void cpasync16(uint32_t dst, const void* src) {
    asm volatile("cp.async.cg.shared.global [%0], [%1], 16;" :: "r"(dst), "l"(src));
}
#define CP_COMMIT() asm volatile("cp.async.commit_group;" ::: "memory")
#define CP_WAIT(n)  asm volatile("cp.async.wait_group %0;" :: "n"(n) : "memory")
#define LDSM_X4(r, addr)                                                              \
    asm volatile("ldmatrix.sync.aligned.m8n8.x4.shared.b16 {%0,%1,%2,%3}, [%4];"      \
                 : "=r"((r)[0]), "=r"((r)[1]), "=r"((r)[2]), "=r"((r)[3]) : "r"(addr))

// ---------------------------------------------------------------------------
// Prepass (frozen, round-10 version): W -> fp16, K -> fp16 [bh][s][d],
// V -> fp16 transposed [bh][d][s].
// ---------------------------------------------------------------------------
__global__ void __launch_bounds__(256)
prep_kernel(const float* __restrict__ K, const float* __restrict__ V,
            const float* __restrict__ W) {
    __shared__ float sv[64 * 65];
    const int tid = threadIdx.x;
    const int cta = blockIdx.x;

    // W -> Wh (1024 CTAs x 1024 elems = exact cover)
    {
        size_t base = (size_t)cta * 1024 + tid * 4;
        float4 w4 = *(const float4*)(W + base);
        *(uint2*)(g_Wh + base) = make_uint2(packh2(w4.x, w4.y), packh2(w4.z, w4.w));
    }

    const int bh = cta >> 5, kt = cta & 31;
    const int b = bh >> 4, h = bh & 15;
    const int n0 = kt * 64;
    const float* Kg = K + (size_t)b * Sn * Dn + h * 64;
    const float* Vg = V + (size_t)b * Sn * Dn + h * 64;

    __half* kd = g_Kh + (size_t)bh * Sn * 64 + (size_t)n0 * 64;
#pragma unroll
    for (int j = 0; j < 4; j++) {
        int idx = j * 256 + tid;
        int r = idx >> 4, c4 = (idx & 15) * 4;
        float4 kv = *(const float4*)(Kg + (size_t)(n0 + r) * Dn + c4);
        *(uint2*)(kd + r * 64 + c4) = make_uint2(packh2(kv.x, kv.y), packh2(kv.z, kv.w));
    }

#pragma unroll
    for (int j = 0; j < 4; j++) {
        int idx = j * 256 + tid;
        int r = idx >> 4, c4 = (idx & 15) * 4;
        float4 vv = *(const float4*)(Vg + (size_t)(n0 + r) * Dn + c4);
        sv[r * 65 + c4 + 0] = vv.x;
        sv[r * 65 + c4 + 1] = vv.y;
        sv[r * 65 + c4 + 2] = vv.z;
        sv[r * 65 + c4 + 3] = vv.w;
    }
    __syncthreads();
    {
        const int d = tid >> 2;
        const int kc = (tid & 3) * 16;
        __half* vd = g_Vth + (size_t)bh * 64 * Sn + (size_t)d * Sn + n0 + kc;
        uint32_t o[8];
#pragma unroll
        for (int k = 0; k < 8; k++)
            o[k] = packh2(sv[(kc + 2 * k) * 65 + d], sv[(kc + 2 * k + 1) * 65 + d]);
        *(uint4*)(vd) = make_uint4(o[0], o[1], o[2], o[3]);
        *(uint4*)(vd + 8) = make_uint4(o[4], o[5], o[6], o[7]);
    }
}

// ---------------------------------------------------------------------------
// Attention (frozen, round-12 version): CTA = one (b,h) x 64 q-rows
// (grid 1024 -> near-ideal SM balance). 128 threads = 4 warps x 16 rows.
// BN=128 keys/iter, 8 chunks between barriers. QK fp16 accumulators +
// in-place ex2.f16x2; PV fp32 accumulators.
// SMEM: Kst[2][128x72] | Vst[2][64x136] (71680 B, occ 3).
// ---------------------------------------------------------------------------
__global__ void __launch_bounds__(128, 3)
attn_kernel(const float* __restrict__ Q) {
    extern __shared__ char sm[];
    __half* Kst = (__half*)sm;                 // 2 x 18432 B
    __half* Vst = (__half*)(sm + 36864);       // 2 x 17408 B

    const int tid = threadIdx.x;
    const int lane = tid & 31, warp = tid >> 5;
    const int g = lane >> 2, t = lane & 3;
    const int lr = lane & 7;
    const int bh = blockIdx.y;
    const int b = bh >> 4, h = bh & 15;
    const int q0 = blockIdx.x * 64;
    const int arow = warp * 16;

    const __half* Kg = g_Kh + (size_t)bh * Sn * 64;
    const __half* VTg = g_Vth + (size_t)bh * 64 * Sn;

    const uint32_t kst_u = smem_u32(Kst);
    const uint32_t vst_u = smem_u32(Vst);

    // prologue: stage 0 of K [128x64] and Vt [64x128]
#pragma unroll
    for (int j = 0; j < 8; j++) {
        int idx = j * 128 + tid;
        int kr = idx >> 3, kc = (idx & 7) * 8;
        cpasync16(kst_u + (uint32_t)(kr * KSTR + kc) * 2, Kg + (size_t)kr * 64 + kc);
        int vr = idx >> 4, vc = (idx & 15) * 8;
        cpasync16(vst_u + (uint32_t)(vr * VSTR + vc) * 2, VTg + (size_t)vr * Sn + vc);
    }
    CP_COMMIT();

    // Q fragments -> registers (scaled 1/8 * log2e), 1 m-frag (16 rows)
    uint32_t qa[4][4];
    {
        const float* q_lo = Q + ((size_t)b * Sn + q0 + arow + g) * Dn + h * 64 + 2 * t;
        const float* q_hi = q_lo + 8 * Dn;
#pragma unroll
        for (int ksp = 0; ksp < 4; ksp++) {
            float2 x0 = *(const float2*)(q_lo + ksp * 16);
            float2 x1 = *(const float2*)(q_hi + ksp * 16);
            float2 x2 = *(const float2*)(q_lo + ksp * 16 + 8);
            float2 x3 = *(const float2*)(q_hi + ksp * 16 + 8);
            qa[ksp][0] = packh2(x0.x * QSCALE, x0.y * QSCALE);
            qa[ksp][1] = packh2(x1.x * QSCALE, x1.y * QSCALE);
            qa[ksp][2] = packh2(x2.x * QSCALE, x2.y * QSCALE);
            qa[ksp][3] = packh2(x3.x * QSCALE, x3.y * QSCALE);
        }
    }

    float o[8][4];
    float lsum0 = 0.0f, lsum1 = 0.0f;
#pragma unroll
    for (int n = 0; n < 8; n++)
#pragma unroll
        for (int j = 0; j < 4; j++) o[n][j] = 0.0f;

    const int am_rows = (lane >> 3) & 1;
    const int am_cols = lane >> 4;

    for (int it = 0; it < Sn / 128; ++it) {
        const int st = it & 1;
        CP_WAIT(0);
        __syncthreads();

        if (it + 1 < Sn / 128) {
            const __half* kb = Kg + (size_t)(it + 1) * 128 * 64;
            const __half* vb = VTg + (it + 1) * 128;
            uint32_t kd = kst_u + (uint32_t)(st ^ 1) * (128 * KSTR * 2);
            uint32_t vd = vst_u + (uint32_t)(st ^ 1) * (64 * VSTR * 2);
#pragma unroll
            for (int j = 0; j < 8; j++) {
                int idx = j * 128 + tid;
                int kr = idx >> 3, kc = (idx & 7) * 8;
                cpasync16(kd + (uint32_t)(kr * KSTR + kc) * 2, kb + (size_t)kr * 64 + kc);
                int vr = idx >> 4, vc = (idx & 15) * 8;
                cpasync16(vd + (uint32_t)(vr * VSTR + vc) * 2, vb + (size_t)vr * Sn + vc);
            }
        }
        CP_COMMIT();

        const uint32_t ks_u = kst_u + (uint32_t)st * (128 * KSTR * 2);
        const uint32_t vs_u = vst_u + (uint32_t)st * (64 * VSTR * 2);

        // 8 x 16-key chunks: QK(f16 acc) -> ex2.f16x2 -> PV(f32 acc)
#pragma unroll
        for (int c = 0; c < 8; c++) {
            uint32_t scA[2] = {0u, 0u};
            uint32_t scB[2] = {0u, 0u};
#pragma unroll
            for (int ksp = 0; ksp < 4; ksp++) {
                uint32_t bb[4];
                LDSM_X4(bb, ks_u + (uint32_t)((c * 16 + am_cols * 8 + lr) * KSTR
                                              + ksp * 16 + am_rows * 8) * 2);
                mma16h(scA, qa[ksp], bb[0], bb[1]);
                mma16h(scB, qa[ksp], bb[2], bb[3]);
            }

            // P = 2^s in place (f16 C-frags ARE the PV A-frags)
            uint32_t pa[4];
            pa[0] = ex2h2(scA[0]);
            pa[1] = ex2h2(scA[1]);
            pa[2] = ex2h2(scB[0]);
            pa[3] = ex2h2(scB[1]);
            __half2 s0 = __hadd2(*(__half2*)&pa[0], *(__half2*)&pa[2]);
            __half2 s1 = __hadd2(*(__half2*)&pa[1], *(__half2*)&pa[3]);
            lsum0 += __low2float(s0) + __high2float(s0);
            lsum1 += __low2float(s1) + __high2float(s1);

            // PV: k-block = chunk c (cols c*16.. in Vt)
#pragma unroll
            for (int nfp = 0; nfp < 4; nfp++) {
                uint32_t bb[4];
                LDSM_X4(bb, vs_u + (uint32_t)((nfp * 16 + am_cols * 8 + lr) * VSTR
                                              + c * 16 + am_rows * 8) * 2);
                mma16(o[2 * nfp], pa, bb[0], bb[1]);
                mma16(o[2 * nfp + 1], pa, bb[2], bb[3]);
            }
        }
    }

    // Epilogue: quad-reduce l, normalize, write ctx fp16
    lsum0 += __shfl_xor_sync(0xffffffffu, lsum0, 1);
    lsum0 += __shfl_xor_sync(0xffffffffu, lsum0, 2);
    lsum1 += __shfl_xor_sync(0xffffffffu, lsum1, 1);
    lsum1 += __shfl_xor_sync(0xffffffffu, lsum1, 2);
    const float inv0 = 1.0f / lsum0, inv1 = 1.0f / lsum1;
    const int r = q0 + arow + g;
    __half* d0 = g_ctxh + ((size_t)b * Sn + r) * Dn + h * 64 + 2 * t;
    __half* d1 = g_ctxh + ((size_t)b * Sn + r + 8) * Dn + h * 64 + 2 * t;
#pragma unroll
    for (int nf = 0; nf < 8; nf++) {
        *(uint32_t*)(d0 + nf * 8) = packh2(o[nf][0] * inv0, o[nf][1] * inv0);
        *(uint32_t*)(d1 + nf * 8) = packh2(o[nf][2] * inv1, o[nf][3] * inv1);
    }
}

// ---------------------------------------------------------------------------
// Projection: out[4096,1024] = ctx_f16 @ Wh^T + bias.
// 64x64 tiles -> 1024 CTAs (max 7 tiles/SM = 14.3k MMAs ~= ideal 14.2k).
// 128 threads = 4 warps (2x2), warp tile 32x32 (acc 32 regs).
// 3-stage cp.async, 18432 B/stage -> 55296 B -> occ 3.
// ---------------------------------------------------------------------------
__global__ void __launch_bounds__(128, 3)
proj_kernel(const float* __restrict__ bias, float* __restrict__ out) {
    extern __shared__ char psm[];
    const int tid = threadIdx.x, lane = tid & 31, warp = tid >> 5;
    const int g = lane >> 2, t = lane & 3;
    const int lr = lane & 7;
    const int wm = warp >> 1, wn = warp & 1;
    const int j0 = blockIdx.x * 64, i0 = blockIdx.y * 64;
    const int am_rows = (lane >> 3) & 1;
    const int am_cols = lane >> 4;

    const __half* Ab = g_ctxh + (size_t)i0 * Dn;
    const __half* Bb = g_Wh + (size_t)j0 * Dn;
    const uint32_t sbase = smem_u32(psm);

    // stage: A 64x72 halves (9216 B) + B 64x72 (9216 B) = 18432 B
#define PROJ_ISSUE(c, s)                                                           \
    do {                                                                           \
        uint32_t ab = sbase + (uint32_t)(s) * 18432u;                              \
        uint32_t bbp = ab + 9216u;                                                 \
        _Pragma("unroll")                                                          \
        for (int j = 0; j < 4; j++) {                                              \
            int idx = j * 128 + tid;                                               \
            int r = idx >> 3, ch = (idx & 7) * 8;                                  \
            cpasync16(ab + (uint32_t)(r * PSTR + ch) * 2,                          \
                      Ab + (size_t)r * Dn + (c) * 64 + ch);                        \
            cpasync16(bbp + (uint32_t)(r * PSTR + ch) * 2,                         \
                      Bb + (size_t)r * Dn + (c) * 64 + ch);                        \
        }                                                                          \
    } while (0)

    float acc[2][4][4];
#pragma unroll
    for (int mf = 0; mf < 2; mf++)
#pragma unroll
        for (int nf = 0; nf < 4; nf++)
#pragma unroll
            for (int j = 0; j < 4; j++) acc[mf][nf][j] = 0.0f;

    PROJ_ISSUE(0, 0);
    CP_COMMIT();
    PROJ_ISSUE(1, 1);
    CP_COMMIT();

    for (int c = 0; c < 16; c++) {
        CP_WAIT(1);
        __syncthreads();
        if (c + 2 < 16) PROJ_ISSUE(c + 2, (c + 2) % 3);
        CP_COMMIT();

        const __half* As = (const __half*)(psm + (c % 3) * 18432);
        const __half* Bs = As + 4608;
#pragma unroll
        for (int ksp = 0; ksp < 4; ksp++) {
            uint32_t a[2][4];
#pragma unroll
            for (int mf = 0; mf < 2; mf++)
                LDSM_X4(a[mf], smem_u32(As + (wm * 32 + mf * 16 + am_rows * 8 + lr) * PSTR
                                           + ksp * 16 + am_cols * 8));
#pragma unroll
            for (int nfp = 0; nfp < 2; nfp++) {
                uint32_t bb[4];
                LDSM_X4(bb, smem_u32(Bs + (wn * 32 + nfp * 16 + am_cols * 8 + lr) * PSTR
                                        + ksp * 16 + am_rows * 8));
#pragma unroll
                for (int mf = 0; mf < 2; mf++) {
                    mma16(acc[mf][2 * nfp], a[mf], bb[0], bb[1]);
                    mma16(acc[mf][2 * nfp + 1], a[mf], bb[2], bb[3]);
                }
            }
        }
    }

#pragma unroll
    for (int mf = 0; mf < 2; mf++) {
        const int r0 = i0 + wm * 32 + mf * 16 + g;
#pragma unroll
        for (int nf = 0; nf < 4; nf++) {
            const int col = j0 + wn * 32 + nf * 8 + 2 * t;
            float b0 = __ldg(bias + col), b1 = __ldg(bias + col + 1);
            *(float2*)(out + (size_t)r0 * Dn + col) =
                make_float2(acc[mf][nf][0] + b0, acc[mf][nf][1] + b1);
            *(float2*)(out + (size_t)(r0 + 8) * Dn + col) =
                make_float2(acc[mf][nf][2] + b0, acc[mf][nf][3] + b1);
        }
    }
#undef PROJ_ISSUE
}

extern "C" void kernel_launch(void* const* d_in, const int* in_sizes, int n_in,
                              void* d_out, int out_size) {
    const float* q    = (const float*)d_in[0];
    const float* k    = (const float*)d_in[1];
    const float* v    = (const float*)d_in[2];
    const float* w    = (const float*)d_in[3];
    const float* bias = (const float*)d_in[4];
    float* out = (float*)d_out;

    const int ASMEM = 73728;   // 2-stage K(128x72) + 2-stage Vt(64x136) fp16
    const int PSMEM = 55296;   // 3 stages x (A 64x72 + B 64x72)
    cudaFuncSetAttribute(attn_kernel, cudaFuncAttributeMaxDynamicSharedMemorySize, ASMEM);
    cudaFuncSetAttribute(proj_kernel, cudaFuncAttributeMaxDynamicSharedMemorySize, PSMEM);

    prep_kernel<<<1024, 256>>>(k, v, w);
    attn_kernel<<<dim3(Sn / 64, Bn * Hn), 128, ASMEM>>>(q);
    proj_kernel<<<dim3(Dn / 64, (Bn * Sn) / 64), 128, PSMEM>>>(bias, out);
}